// round 16
// baseline (speedup 1.0000x reference)
#include <cuda_runtime.h>
#include <cuda_bf16.h>
#include <cstdint>

// ---------------------------------------------------------------------------
// Problem constants
// ---------------------------------------------------------------------------
#define BB 128
#define JJ 8192
#define DD 32
#define HH 128

#define TJ 64       // cells per tile
#define NT 256      // threads per CTA
#define NTILES (BB * (JJ / TJ))   // 16384
#define GRID_MAIN 456             // 152 SMs * 3 CTAs, persistent

// ---------------------------------------------------------------------------
// Scratch (device globals; no allocations allowed)
// ---------------------------------------------------------------------------
__device__ float g_fej[JJ * HH];          // 4 MB (permuted layout)
__device__ float g_num[BB * 4 * DD];
__device__ float g_sumexp[BB * 4];
__device__ int   g_maskcnt[BB];

// ---------------------------------------------------------------------------
// Shared-memory layout (BYTE offsets). bf16 rows are 272B (128 bf16 + 8 pad).
// HOUT rows are 36 floats (144B, 16B-aligned) for float4 access.
// ---------------------------------------------------------------------------
#define SB_H1HI   0                        // 64 * 272 = 17408
#define SB_H1LO   17408                    // -> 34816
#define SB_WHI    34816                    // 32 * 272 = 8704 -> 43520
#define SB_WLO    43520                    // -> 52224
#define SB_HOUT   52224                    // 64*36*4 = 9216 -> 61440 (f32)
#define SB_W10    61440                    // 512
#define SB_LN1W   61952                    // 512
#define SB_LN1B   62464                    // 512
#define SB_LN2W   62976                    // 128
#define SB_LN2B   63104                    // 128
#define SB_HB2    63232                    // 128
#define SB_GW1    63360                    // 2048
#define SB_GB1    65408                    // 64
#define SB_GW2    65472                    // 256
#define SB_GB2    65728                    // 16
#define SB_XS     65744                    // 256
#define SB_ELOG   66000                    // 1024
#define SB_MS     67024                    // 256 (ints)
#define SB_WPOOL  67280                    // 4352
#define SMEM_BYTES 71648

#define F_HOUT  (SB_HOUT/4)
#define F_W10   (SB_W10/4)
#define F_LN1W  (SB_LN1W/4)
#define F_LN1B  (SB_LN1B/4)
#define F_LN2W  (SB_LN2W/4)
#define F_LN2B  (SB_LN2B/4)
#define F_HB2   (SB_HB2/4)
#define F_GW1   (SB_GW1/4)
#define F_GB1   (SB_GB1/4)
#define F_GW2   (SB_GW2/4)
#define F_GB2   (SB_GB2/4)
#define F_XS    (SB_XS/4)
#define F_ELOG  (SB_ELOG/4)
#define F_MS    (SB_MS/4)
#define F_WPOOL (SB_WPOOL/4)

__device__ __forceinline__ uint32_t s2u(const void* p) {
    return (uint32_t)__cvta_generic_to_shared(p);
}
__device__ __forceinline__ uint32_t pack_bf16x2(float vlo, float vhi) {
    uint32_t r;
    asm("cvt.rn.bf16x2.f32 %0, %1, %2;" : "=r"(r) : "f"(vhi), "f"(vlo));
    return r;
}

#define LDSM4(R0,R1,R2,R3,ADDR) \
    asm volatile("ldmatrix.sync.aligned.m8n8.x4.shared.b16 {%0,%1,%2,%3}, [%4];" \
                 : "=r"(R0), "=r"(R1), "=r"(R2), "=r"(R3) : "r"(ADDR))
#define MMA_BF16(CC, A0,A1,A2,A3, B0,B1) \
    asm volatile("mma.sync.aligned.m16n8k16.row.col.f32.bf16.bf16.f32 " \
                 "{%0,%1,%2,%3}, {%4,%5,%6,%7}, {%8,%9}, {%0,%1,%2,%3};" \
                 : "+f"(CC[0]), "+f"(CC[1]), "+f"(CC[2]), "+f"(CC[3]) \
                 : "r"(A0), "r"(A1), "r"(A2), "r"(A3), "r"(B0), "r"(B1))

// ---------------------------------------------------------------------------
// Pads: align ncu -s 5 -c 1 window (2 hidden harness launches) onto k_main
// ---------------------------------------------------------------------------
__global__ void k_padA() {}
__global__ void k_padB() {}

// ---------------------------------------------------------------------------
// Kernel A: build permuted g_fej; blocks 0-63 also zero accumulators
// ---------------------------------------------------------------------------
__global__ void k_fej(const float* __restrict__ fe,
                      const float* __restrict__ h_w1,
                      const float* __restrict__ h_b1) {
    __shared__ float fes[8][33];
    const int j8 = blockIdx.x;
    const int t  = threadIdx.x;          // 256
    if (j8 < 64) {
        const int i = j8 * 256 + t;
        if (i < BB * 4 * DD) g_num[i] = 0.f;
        if (i < BB * 4)      g_sumexp[i] = 0.f;
        if (i < BB)          g_maskcnt[i] = 0;
    }
    fes[t >> 5][t & 31] = fe[(j8 * 8 + (t >> 5)) * DD + (t & 31)];
    __syncthreads();
    const int f  = 4 * t;
    const int i  = f >> 7;
    const int jc = (f >> 4) & 7;
    const int qq = (f >> 2) & 3;
    const int h0 = 32 * qq + 4 * i;
    float4 acc = *reinterpret_cast<const float4*>(&h_b1[h0]);
    const float* fr = fes[jc];
#pragma unroll 8
    for (int d = 0; d < 32; d++) {
        const float4 wv = *reinterpret_cast<const float4*>(&h_w1[(1 + d) * HH + h0]);
        const float fv = fr[d];
        acc.x = fmaf(fv, wv.x, acc.x);
        acc.y = fmaf(fv, wv.y, acc.y);
        acc.z = fmaf(fv, wv.z, acc.z);
        acc.w = fmaf(fv, wv.w, acc.w);
    }
    *reinterpret_cast<float4*>(&g_fej[j8 * 1024 + f]) = acc;
}

// ---------------------------------------------------------------------------
// Kernel B: persistent pipeline; 2-warp tensor-core GEMM (m32 x n32 per warp)
// with hi/lo bf16 split (3 passes) and in-register LN over D=32.
// ---------------------------------------------------------------------------
__global__ void __launch_bounds__(NT, 3)
k_main(const float* __restrict__ x, const int* __restrict__ mask,
       const float* __restrict__ h_w1,
       const float* __restrict__ h_ln1_w, const float* __restrict__ h_ln1_b,
       const float* __restrict__ h_w2,   const float* __restrict__ h_b2,
       const float* __restrict__ h_ln2_w, const float* __restrict__ h_ln2_b,
       const float* __restrict__ gw1,    const float* __restrict__ gb1,
       const float* __restrict__ gw2,    const float* __restrict__ gb2) {
    extern __shared__ char smc[];
    float* smf = (float*)smc;
    int*   smi = (int*)smc;
    const int t  = threadIdx.x;
    const int c = t >> 2, q = t & 3;
    const int w = t >> 5, lane = t & 31, r0 = w * 8;

    // ---- one-time weight staging ----
    for (int idx = t; idx < HH * DD; idx += NT) {   // w2 -> bf16 hi/lo [d][k]
        const int k = idx >> 5, d = idx & 31;
        const float v = h_w2[idx];
        const __nv_bfloat16 hb = __float2bfloat16_rn(v);
        const float r = v - __bfloat162float(hb);
        *(__nv_bfloat16*)(smc + SB_WHI + d * 272 + 2 * k) = hb;
        *(__nv_bfloat16*)(smc + SB_WLO + d * 272 + 2 * k) = __float2bfloat16_rn(r);
    }
    if (t < HH) {
        smf[F_W10 + t]  = h_w1[t];
        smf[F_LN1W + t] = h_ln1_w[t];
        smf[F_LN1B + t] = h_ln1_b[t];
    }
    if (t < DD) {
        smf[F_LN2W + t] = h_ln2_w[t];
        smf[F_LN2B + t] = h_ln2_b[t];
        smf[F_HB2 + t]  = h_b2[t];
    }
    for (int i = t; i < 512; i += NT) smf[F_GW1 + i] = gw1[i];
    if (t < 16) smf[F_GB1 + t] = gb1[t];
    if (t < 64) smf[F_GW2 + t] = gw2[t];
    if (t < 4)  smf[F_GB2 + t] = gb2[t];

    const float4* fj4 = reinterpret_cast<const float4*>(g_fej);

    // ldmatrix bases (constant across tiles); GEMM warps are w = 0,1 (m32 each)
    const uint32_t aAddrHi0 = s2u(smc + SB_H1HI) + (32 * w + (lane & 15)) * 272 + ((lane >> 4) * 16);
    const uint32_t aAddrHi1 = aAddrHi0 + 16 * 272;
    const uint32_t aAddrLo0 = aAddrHi0 + (SB_H1LO - SB_H1HI);
    const uint32_t aAddrLo1 = aAddrHi1 + (SB_H1LO - SB_H1HI);
    const uint32_t bRow = 8 * (lane >> 4) + (lane & 7);
    const uint32_t bCol = ((lane >> 3) & 1) * 16;
    const uint32_t bHiG0 = s2u(smc + SB_WHI) + bRow * 272 + bCol;           // n 0-15
    const uint32_t bHiG1 = s2u(smc + SB_WHI) + (16 + bRow) * 272 + bCol;    // n 16-31
    const uint32_t bLoG0 = bHiG0 + (SB_WLO - SB_WHI);
    const uint32_t bLoG1 = bHiG1 + (SB_WLO - SB_WHI);

    for (int tile = blockIdx.x; tile < NTILES; tile += GRID_MAIN) {
        const int b  = tile >> 7;
        const int j0 = (tile & 127) * TJ;

        if (t < TJ) {
            smf[F_XS + t] = x[b * JJ + j0 + t];
            smi[F_MS + t] = mask[b * JJ + j0 + t];
        }
        __syncthreads();   // B1: XS/MS published; prev-iter smem reuse fenced

        // ---- phase 1: pre = x*w1_0 + fej ; LN(128) ; relu -> bf16 hi/lo ----
        {
            const int fbase = ((j0 + c) >> 3) * 256 + (c & 7) * 4 + q;
            const float xv = smf[F_XS + c];
            float4 pv[8];
            float s = 0.f, ss = 0.f;
#pragma unroll
            for (int i = 0; i < 8; i++) {
                float4 f = fj4[fbase + 32 * i];
                const float4 wv = *reinterpret_cast<const float4*>(&smf[F_W10 + q * 32 + 4 * i]);
                float4 v;
                v.x = fmaf(xv, wv.x, f.x);
                v.y = fmaf(xv, wv.y, f.y);
                v.z = fmaf(xv, wv.z, f.z);
                v.w = fmaf(xv, wv.w, f.w);
                pv[i] = v;
                s  += (v.x + v.y) + (v.z + v.w);
                ss += v.x * v.x + v.y * v.y + v.z * v.z + v.w * v.w;
            }
            s  += __shfl_xor_sync(0xffffffffu, s, 1);
            s  += __shfl_xor_sync(0xffffffffu, s, 2);
            ss += __shfl_xor_sync(0xffffffffu, ss, 1);
            ss += __shfl_xor_sync(0xffffffffu, ss, 2);
            const float mean = s * (1.f / 128.f);
            const float var  = ss * (1.f / 128.f) - mean * mean;
            const float rstd = rsqrtf(var + 1e-5f);
            uint32_t hi[16], lo[16];
#pragma unroll
            for (int i = 0; i < 8; i++) {
                float4 v = pv[i];
                const float4 lw = *reinterpret_cast<const float4*>(&smf[F_LN1W + q * 32 + 4 * i]);
                const float4 lb = *reinterpret_cast<const float4*>(&smf[F_LN1B + q * 32 + 4 * i]);
                const float o0 = fmaxf(0.f, fmaf((v.x - mean) * rstd, lw.x, lb.x));
                const float o1 = fmaxf(0.f, fmaf((v.y - mean) * rstd, lw.y, lb.y));
                const float o2 = fmaxf(0.f, fmaf((v.z - mean) * rstd, lw.z, lb.z));
                const float o3 = fmaxf(0.f, fmaf((v.w - mean) * rstd, lw.w, lb.w));
                const __nv_bfloat16 h0 = __float2bfloat16_rn(o0);
                const __nv_bfloat16 h1 = __float2bfloat16_rn(o1);
                const __nv_bfloat16 h2 = __float2bfloat16_rn(o2);
                const __nv_bfloat16 h3 = __float2bfloat16_rn(o3);
                hi[2*i]   = pack_bf16x2(o0, o1);
                hi[2*i+1] = pack_bf16x2(o2, o3);
                lo[2*i]   = pack_bf16x2(o0 - __bfloat162float(h0), o1 - __bfloat162float(h1));
                lo[2*i+1] = pack_bf16x2(o2 - __bfloat162float(h2), o3 - __bfloat162float(h3));
            }
            char* hdst = smc + SB_H1HI + c * 272 + 64 * q;
            char* ldst = smc + SB_H1LO + c * 272 + 64 * q;
#pragma unroll
            for (int sIdx = 0; sIdx < 4; sIdx++) {
                *reinterpret_cast<uint4*>(hdst + 16 * sIdx) =
                    make_uint4(hi[4*sIdx], hi[4*sIdx+1], hi[4*sIdx+2], hi[4*sIdx+3]);
                *reinterpret_cast<uint4*>(ldst + 16 * sIdx) =
                    make_uint4(lo[4*sIdx], lo[4*sIdx+1], lo[4*sIdx+2], lo[4*sIdx+3]);
            }
        }
        __syncthreads();   // B2: h1 planes visible to MMA warps

        // ---- phase 2+3: warps 0-1: m32 x n32 GEMM + in-register LN ----
        if (w < 2) {
            float acc[2][4][4];
#pragma unroll
            for (int mi = 0; mi < 2; mi++)
#pragma unroll
                for (int tl = 0; tl < 4; tl++)
#pragma unroll
                    for (int p = 0; p < 4; p++) acc[mi][tl][p] = 0.f;
            uint32_t aH0 = aAddrHi0, aH1 = aAddrHi1, aL0 = aAddrLo0, aL1 = aAddrLo1;
            uint32_t b00 = bHiG0, b01 = bHiG1, b10 = bLoG0, b11 = bLoG1;
#pragma unroll
            for (int ks = 0; ks < 8; ks++) {
                uint32_t x0, x1, x2, x3, y0, y1, y2, y3;       // A hi m16 tiles
                uint32_t u0, u1, u2, u3, v0, v1, v2, v3;       // A lo m16 tiles
                uint32_t p0, p1, p2, p3, p4, p5, p6, p7;       // B hi g0,g1
                uint32_t m0, m1, m2, m3, m4, m5, m6, m7;       // B lo g0,g1
                LDSM4(x0, x1, x2, x3, aH0);
                LDSM4(y0, y1, y2, y3, aH1);
                LDSM4(u0, u1, u2, u3, aL0);
                LDSM4(v0, v1, v2, v3, aL1);
                LDSM4(p0, p1, p2, p3, b00);
                LDSM4(p4, p5, p6, p7, b01);
                LDSM4(m0, m1, m2, m3, b10);
                LDSM4(m4, m5, m6, m7, b11);
                // m16 tile 0 (rows 32w+0..15)
                MMA_BF16(acc[0][0], x0, x1, x2, x3, p0, p1);
                MMA_BF16(acc[0][1], x0, x1, x2, x3, p2, p3);
                MMA_BF16(acc[0][2], x0, x1, x2, x3, p4, p5);
                MMA_BF16(acc[0][3], x0, x1, x2, x3, p6, p7);
                MMA_BF16(acc[0][0], x0, x1, x2, x3, m0, m1);
                MMA_BF16(acc[0][1], x0, x1, x2, x3, m2, m3);
                MMA_BF16(acc[0][2], x0, x1, x2, x3, m4, m5);
                MMA_BF16(acc[0][3], x0, x1, x2, x3, m6, m7);
                MMA_BF16(acc[0][0], u0, u1, u2, u3, p0, p1);
                MMA_BF16(acc[0][1], u0, u1, u2, u3, p2, p3);
                MMA_BF16(acc[0][2], u0, u1, u2, u3, p4, p5);
                MMA_BF16(acc[0][3], u0, u1, u2, u3, p6, p7);
                // m16 tile 1 (rows 32w+16..31)
                MMA_BF16(acc[1][0], y0, y1, y2, y3, p0, p1);
                MMA_BF16(acc[1][1], y0, y1, y2, y3, p2, p3);
                MMA_BF16(acc[1][2], y0, y1, y2, y3, p4, p5);
                MMA_BF16(acc[1][3], y0, y1, y2, y3, p6, p7);
                MMA_BF16(acc[1][0], y0, y1, y2, y3, m0, m1);
                MMA_BF16(acc[1][1], y0, y1, y2, y3, m2, m3);
                MMA_BF16(acc[1][2], y0, y1, y2, y3, m4, m5);
                MMA_BF16(acc[1][3], y0, y1, y2, y3, m6, m7);
                MMA_BF16(acc[1][0], v0, v1, v2, v3, p0, p1);
                MMA_BF16(acc[1][1], v0, v1, v2, v3, p2, p3);
                MMA_BF16(acc[1][2], v0, v1, v2, v3, p4, p5);
                MMA_BF16(acc[1][3], v0, v1, v2, v3, p6, p7);
                aH0 += 32; aH1 += 32; aL0 += 32; aL1 += 32;
                b00 += 32; b01 += 32; b10 += 32; b11 += 32;
            }
            // in-register LN over D=32: per m16 tile, rows rA and rA+8
            const int j3 = lane & 3;
#pragma unroll
            for (int mi = 0; mi < 2; mi++) {
                const int rA = 32 * w + 16 * mi + (lane >> 2);
                float vA[8], vB[8];
                float s1A = 0.f, s2A = 0.f, s1B = 0.f, s2B = 0.f;
#pragma unroll
                for (int tl = 0; tl < 4; tl++) {
                    const int col0 = 8 * tl + 2 * j3;
                    const float2 hb = *reinterpret_cast<const float2*>(&smf[F_HB2 + col0]);
                    vA[2*tl]   = acc[mi][tl][0] + hb.x;
                    vA[2*tl+1] = acc[mi][tl][1] + hb.y;
                    vB[2*tl]   = acc[mi][tl][2] + hb.x;
                    vB[2*tl+1] = acc[mi][tl][3] + hb.y;
                    s1A += vA[2*tl] + vA[2*tl+1];
                    s2A = fmaf(vA[2*tl], vA[2*tl], fmaf(vA[2*tl+1], vA[2*tl+1], s2A));
                    s1B += vB[2*tl] + vB[2*tl+1];
                    s2B = fmaf(vB[2*tl], vB[2*tl], fmaf(vB[2*tl+1], vB[2*tl+1], s2B));
                }
                s1A += __shfl_xor_sync(0xffffffffu, s1A, 1);
                s1A += __shfl_xor_sync(0xffffffffu, s1A, 2);
                s2A += __shfl_xor_sync(0xffffffffu, s2A, 1);
                s2A += __shfl_xor_sync(0xffffffffu, s2A, 2);
                s1B += __shfl_xor_sync(0xffffffffu, s1B, 1);
                s1B += __shfl_xor_sync(0xffffffffu, s1B, 2);
                s2B += __shfl_xor_sync(0xffffffffu, s2B, 1);
                s2B += __shfl_xor_sync(0xffffffffu, s2B, 2);
                const float meanA = s1A * (1.f / 32.f);
                const float rstdA = rsqrtf(s2A * (1.f / 32.f) - meanA * meanA + 1e-5f);
                const float meanB = s1B * (1.f / 32.f);
                const float rstdB = rsqrtf(s2B * (1.f / 32.f) - meanB * meanB + 1e-5f);
#pragma unroll
                for (int tl = 0; tl < 4; tl++) {
                    const int col0 = 8 * tl + 2 * j3;
                    const float2 lw = *reinterpret_cast<const float2*>(&smf[F_LN2W + col0]);
                    const float2 lb = *reinterpret_cast<const float2*>(&smf[F_LN2B + col0]);
                    float2 oA, oB;
                    oA.x = fmaxf(0.f, fmaf((vA[2*tl]   - meanA) * rstdA, lw.x, lb.x));
                    oA.y = fmaxf(0.f, fmaf((vA[2*tl+1] - meanA) * rstdA, lw.y, lb.y));
                    oB.x = fmaxf(0.f, fmaf((vB[2*tl]   - meanB) * rstdB, lw.x, lb.x));
                    oB.y = fmaxf(0.f, fmaf((vB[2*tl+1] - meanB) * rstdB, lw.y, lb.y));
                    *reinterpret_cast<float2*>(&smf[F_HOUT + rA * 36 + col0])       = oA;
                    *reinterpret_cast<float2*>(&smf[F_HOUT + (rA + 8) * 36 + col0]) = oB;
                }
            }
        }
        __syncthreads();   // B3: hout visible to all warps

        // ---- phase 4: gate MLP -> logits -> clip -> mask -> exp ----
        float se;
        int   cnt;
        {
            const float4* hrow4 = reinterpret_cast<const float4*>(&smf[F_HOUT + c * 36]);
            float g1v[4];
#pragma unroll
            for (int e = 0; e < 4; e++) g1v[e] = smf[F_GB1 + 4 * q + e];
#pragma unroll
            for (int i = 0; i < 8; i++) {
                const float4 h4 = hrow4[i];
#pragma unroll
                for (int ccc = 0; ccc < 4; ccc++) {
                    const float hvv = (ccc == 0) ? h4.x : (ccc == 1) ? h4.y : (ccc == 2) ? h4.z : h4.w;
                    const float4 gw = *reinterpret_cast<const float4*>(&smf[F_GW1 + (4 * i + ccc) * 16 + 4 * q]);
                    g1v[0] = fmaf(hvv, gw.x, g1v[0]);
                    g1v[1] = fmaf(hvv, gw.y, g1v[1]);
                    g1v[2] = fmaf(hvv, gw.z, g1v[2]);
                    g1v[3] = fmaf(hvv, gw.w, g1v[3]);
                }
            }
            float pl[4] = {0.f, 0.f, 0.f, 0.f};
#pragma unroll
            for (int e = 0; e < 4; e++) {
                const float gv = fmaxf(0.f, g1v[e]);
                const float4 g2 = *reinterpret_cast<const float4*>(&smf[F_GW2 + (4 * q + e) * 4]);
                pl[0] = fmaf(gv, g2.x, pl[0]);
                pl[1] = fmaf(gv, g2.y, pl[1]);
                pl[2] = fmaf(gv, g2.z, pl[2]);
                pl[3] = fmaf(gv, g2.w, pl[3]);
            }
#pragma unroll
            for (int k = 0; k < 4; k++) {
                pl[k] += __shfl_xor_sync(0xffffffffu, pl[k], 1);
                pl[k] += __shfl_xor_sync(0xffffffffu, pl[k], 2);
            }
            const int mval = smi[F_MS + c];
            const float raw = pl[q] + smf[F_GB2 + q];
            const float lgt = fminf(10.f, fmaxf(-10.f, raw));
            const float ev  = (mval > 0) ? __expf(lgt) : 0.f;
            smf[F_ELOG + c * 4 + q] = ev;
            se = ev;
            se += __shfl_xor_sync(0xffffffffu, se, 4);
            se += __shfl_xor_sync(0xffffffffu, se, 8);
            se += __shfl_xor_sync(0xffffffffu, se, 16);
            const unsigned bal = __ballot_sync(0xffffffffu, (q == 0) && (mval > 0));
            cnt = (int)__popc(bal);
        }
        __syncwarp();

        // ---- phase 5: pooling partials into warp-own scratch ----
        {
            float p0 = 0.f, p1 = 0.f, p2 = 0.f, p3 = 0.f;
#pragma unroll
            for (int rr = 0; rr < 8; rr++) {
                const float4 ev = *reinterpret_cast<const float4*>(&smf[F_ELOG + (r0 + rr) * 4]);
                const float h = smf[F_HOUT + (r0 + rr) * 36 + lane];
                p0 = fmaf(ev.x, h, p0);
                p1 = fmaf(ev.y, h, p1);
                p2 = fmaf(ev.z, h, p2);
                p3 = fmaf(ev.w, h, p3);
            }
            float* wn = &smf[F_WPOOL + w * 136];
            wn[0 * 32 + lane] = p0;
            wn[1 * 32 + lane] = p1;
            wn[2 * 32 + lane] = p2;
            wn[3 * 32 + lane] = p3;
            if (lane < 4) wn[128 + lane] = se;
            if (lane == 0) ((int*)wn)[132] = cnt;
        }
        __syncthreads();   // B4

        // ---- phase 6: cross-warp reduce + global RED ----
        if (t < 128) {
            float a = 0.f;
#pragma unroll
            for (int ww = 0; ww < 8; ww++) a += smf[F_WPOOL + ww * 136 + t];
            atomicAdd(&g_num[b * 128 + t], a);
        } else if (t < 132) {
            const int hq = t - 128;
            float a = 0.f;
#pragma unroll
            for (int ww = 0; ww < 8; ww++) a += smf[F_WPOOL + ww * 136 + 128 + hq];
            atomicAdd(&g_sumexp[b * 4 + hq], a);
        } else if (t == 132) {
            int a = 0;
#pragma unroll
            for (int ww = 0; ww < 8; ww++) a += ((int*)&smf[F_WPOOL + ww * 136])[132];
            atomicAdd(&g_maskcnt[b], a);
        }
    }
}

// ---------------------------------------------------------------------------
// Kernel C: per-batch tail  head_sums -> comb -> e1 -> e2 -> (mu, logvar)
// ---------------------------------------------------------------------------
__global__ void k_tail(const float* __restrict__ c_w,    const float* __restrict__ c_b,
                       const float* __restrict__ c_ln_w, const float* __restrict__ c_ln_b,
                       const float* __restrict__ e_w1,   const float* __restrict__ e_b1,
                       const float* __restrict__ e_ln1_w, const float* __restrict__ e_ln1_b,
                       const float* __restrict__ e_w2,   const float* __restrict__ e_b2,
                       const float* __restrict__ e_ln2_w, const float* __restrict__ e_ln2_b,
                       float* __restrict__ out) {
    const int b = blockIdx.x;
    const int t = threadIdx.x;      // 256
    __shared__ float hs[128];
    __shared__ float comb[32];
    __shared__ float h2s[256];
    __shared__ float red[16];
    __shared__ float part[256];

    const int mc = g_maskcnt[b];
    if (t < 128) {
        const float den = g_sumexp[b * 4 + (t >> 5)];
        hs[t] = (mc > 0) ? g_num[b * 128 + t] / den : 0.f;
    }
    __syncthreads();

    {
        const int o = t & 31, kg = t >> 5;
        float a = 0.f;
#pragma unroll
        for (int k = 0; k < 16; k++)
            a = fmaf(hs[kg * 16 + k], c_w[(kg * 16 + k) * 32 + o], a);
        part[kg * 32 + o] = a;
    }
    __syncthreads();
    if (t < 32) {
        float a = c_b[t];
#pragma unroll
        for (int g = 0; g < 8; g++) a += part[g * 32 + t];
        float s1 = a, s2 = a * a;
#pragma unroll
        for (int m = 16; m > 0; m >>= 1) {
            s1 += __shfl_xor_sync(0xffffffffu, s1, m);
            s2 += __shfl_xor_sync(0xffffffffu, s2, m);
        }
        const float mean = s1 * (1.f / 32.f);
        const float var  = s2 * (1.f / 32.f) - mean * mean;
        const float r = rsqrtf(var + 1e-5f);
        const float v = fmaxf(0.f, fmaf((a - mean) * r, c_ln_w[t], c_ln_b[t]));
        comb[t] = (mc > 0) ? v : 0.f;
    }
    __syncthreads();

    {
        float a = e_b1[t];
#pragma unroll
        for (int k = 0; k < 32; k++) a = fmaf(comb[k], e_w1[k * 256 + t], a);
        float s1 = a, s2 = a * a;
#pragma unroll
        for (int m = 16; m > 0; m >>= 1) {
            s1 += __shfl_xor_sync(0xffffffffu, s1, m);
            s2 += __shfl_xor_sync(0xffffffffu, s2, m);
        }
        if ((t & 31) == 0) { red[t >> 5] = s1; red[8 + (t >> 5)] = s2; }
        __syncthreads();
        float S = 0.f, SS = 0.f;
#pragma unroll
        for (int i = 0; i < 8; i++) { S += red[i]; SS += red[8 + i]; }
        const float mean = S * (1.f / 256.f);
        const float var  = SS * (1.f / 256.f) - mean * mean;
        const float r = rsqrtf(var + 1e-5f);
        h2s[t] = fmaxf(0.f, fmaf((a - mean) * r, e_ln1_w[t], e_ln1_b[t]));
    }
    __syncthreads();

    {
        const int o = t & 63, kg = t >> 6;
        float a = 0.f;
#pragma unroll 8
        for (int k = 0; k < 64; k++)
            a = fmaf(h2s[kg * 64 + k], e_w2[(kg * 64 + k) * 64 + o], a);
        part[kg * 64 + o] = a;
    }
    __syncthreads();
    float oacc = 0.f;
    if (t < 64) {
        oacc = e_b2[t] + part[t] + part[64 + t] + part[128 + t] + part[192 + t];
        float s1 = oacc, s2 = oacc * oacc;
#pragma unroll
        for (int m = 16; m > 0; m >>= 1) {
            s1 += __shfl_xor_sync(0xffffffffu, s1, m);
            s2 += __shfl_xor_sync(0xffffffffu, s2, m);
        }
        if ((t & 31) == 0) { red[t >> 5] = s1; red[8 + (t >> 5)] = s2; }
    }
    __syncthreads();
    if (t < 64) {
        const float S  = red[0] + red[1];
        const float SS = red[8] + red[9];
        const float mean = S * (1.f / 64.f);
        const float var  = SS * (1.f / 64.f) - mean * mean;
        const float r = rsqrtf(var + 1e-5f);
        const float o = fmaxf(0.f, fmaf((oacc - mean) * r, e_ln2_w[t], e_ln2_b[t]));
        out[(t >> 5) * (BB * 32) + b * 32 + (t & 31)] = o;
    }
}

// ---------------------------------------------------------------------------
// Launch: fej(1), padA(2), padB(3), main(4 -> process #6, profiled), tail(5)
// ---------------------------------------------------------------------------
extern "C" void kernel_launch(void* const* d_in, const int* in_sizes, int n_in,
                              void* d_out, int out_size) {
    const float* x       = (const float*)d_in[0];
    const int*   mask    = (const int*)  d_in[1];
    const float* fe      = (const float*)d_in[2];
    const float* h_w1    = (const float*)d_in[3];
    const float* h_b1    = (const float*)d_in[4];
    const float* h_ln1_w = (const float*)d_in[5];
    const float* h_ln1_b = (const float*)d_in[6];
    const float* h_w2    = (const float*)d_in[7];
    const float* h_b2    = (const float*)d_in[8];
    const float* h_ln2_w = (const float*)d_in[9];
    const float* h_ln2_b = (const float*)d_in[10];
    const float* g_w1    = (const float*)d_in[11];
    const float* g_b1    = (const float*)d_in[12];
    const float* g_w2    = (const float*)d_in[13];
    const float* g_b2    = (const float*)d_in[14];
    const float* c_w     = (const float*)d_in[15];
    const float* c_b     = (const float*)d_in[16];
    const float* c_ln_w  = (const float*)d_in[17];
    const float* c_ln_b  = (const float*)d_in[18];
    const float* e_w1    = (const float*)d_in[19];
    const float* e_b1    = (const float*)d_in[20];
    const float* e_ln1_w = (const float*)d_in[21];
    const float* e_ln1_b = (const float*)d_in[22];
    const float* e_w2    = (const float*)d_in[23];
    const float* e_b2    = (const float*)d_in[24];
    const float* e_ln2_w = (const float*)d_in[25];
    const float* e_ln2_b = (const float*)d_in[26];
    float* out = (float*)d_out;

    cudaFuncSetAttribute(k_main, cudaFuncAttributeMaxDynamicSharedMemorySize, SMEM_BYTES);

    k_fej<<<JJ / 8, 256>>>(fe, h_w1, h_b1);      // 1
    k_padA<<<1, 32>>>();                         // 2
    k_padB<<<1, 32>>>();                         // 3
    k_main<<<GRID_MAIN, NT, SMEM_BYTES>>>(x, mask, h_w1, h_ln1_w, h_ln1_b,  // 4
                                          h_w2, h_b2, h_ln2_w, h_ln2_b,
                                          g_w1, g_b1, g_w2, g_b2);
    k_tail<<<BB, 256>>>(c_w, c_b, c_ln_w, c_ln_b,                           // 5
                        e_w1, e_b1, e_ln1_w, e_ln1_b,
                        e_w2, e_b2, e_ln2_w, e_ln2_b, out);
}

// round 17
// speedup vs baseline: 1.0090x; 1.0090x over previous
#include <cuda_runtime.h>
#include <cuda_bf16.h>
#include <cstdint>

// ---------------------------------------------------------------------------
// Problem constants
// ---------------------------------------------------------------------------
#define BB 128
#define JJ 8192
#define DD 32
#define HH 128

#define TJ 64       // cells per tile
#define NT 256      // threads per CTA
#define NTILES (BB * (JJ / TJ))   // 16384
#define GRID_MAIN 456             // 152 SMs * 3 CTAs, persistent

// ---------------------------------------------------------------------------
// Scratch (device globals; no allocations allowed)
// ---------------------------------------------------------------------------
__device__ float g_fej[JJ * HH];          // 4 MB (permuted layout)
__device__ float g_num[BB * 4 * DD];
__device__ float g_sumexp[BB * 4];
__device__ int   g_maskcnt[BB];

// ---------------------------------------------------------------------------
// Shared-memory layout (BYTE offsets). bf16 rows are 272B (128 bf16 + 8 pad).
// HOUT rows are 36 floats (144B, 16B-aligned) for float4 access.
// ---------------------------------------------------------------------------
#define SB_H1HI   0                        // 64 * 272 = 17408
#define SB_H1LO   17408                    // -> 34816
#define SB_WHI    34816                    // 32 * 272 = 8704 -> 43520
#define SB_WLO    43520                    // -> 52224
#define SB_HOUT   52224                    // 64*36*4 = 9216 -> 61440 (f32)
#define SB_W10    61440                    // 512
#define SB_LN1W   61952                    // 512
#define SB_LN1B   62464                    // 512
#define SB_LN2W   62976                    // 128
#define SB_LN2B   63104                    // 128
#define SB_HB2    63232                    // 128
#define SB_GW1    63360                    // 2048
#define SB_GB1    65408                    // 64
#define SB_GW2    65472                    // 256
#define SB_GB2    65728                    // 16
#define SB_XS     65744                    // 256
#define SB_ELOG   66000                    // 1024
#define SB_MS     67024                    // 256 (ints)
#define SB_WPOOL  67280                    // 4352
#define SMEM_BYTES 71648

#define F_HOUT  (SB_HOUT/4)
#define F_W10   (SB_W10/4)
#define F_LN1W  (SB_LN1W/4)
#define F_LN1B  (SB_LN1B/4)
#define F_LN2W  (SB_LN2W/4)
#define F_LN2B  (SB_LN2B/4)
#define F_HB2   (SB_HB2/4)
#define F_GW1   (SB_GW1/4)
#define F_GB1   (SB_GB1/4)
#define F_GW2   (SB_GW2/4)
#define F_GB2   (SB_GB2/4)
#define F_XS    (SB_XS/4)
#define F_ELOG  (SB_ELOG/4)
#define F_MS    (SB_MS/4)
#define F_WPOOL (SB_WPOOL/4)

__device__ __forceinline__ uint32_t s2u(const void* p) {
    return (uint32_t)__cvta_generic_to_shared(p);
}
__device__ __forceinline__ uint32_t pack_bf16x2(float vlo, float vhi) {
    uint32_t r;
    asm("cvt.rn.bf16x2.f32 %0, %1, %2;" : "=r"(r) : "f"(vhi), "f"(vlo));
    return r;
}

#define LDSM4(R0,R1,R2,R3,ADDR) \
    asm volatile("ldmatrix.sync.aligned.m8n8.x4.shared.b16 {%0,%1,%2,%3}, [%4];" \
                 : "=r"(R0), "=r"(R1), "=r"(R2), "=r"(R3) : "r"(ADDR))
#define MMA_BF16(CC, A0,A1,A2,A3, B0,B1) \
    asm volatile("mma.sync.aligned.m16n8k16.row.col.f32.bf16.bf16.f32 " \
                 "{%0,%1,%2,%3}, {%4,%5,%6,%7}, {%8,%9}, {%0,%1,%2,%3};" \
                 : "+f"(CC[0]), "+f"(CC[1]), "+f"(CC[2]), "+f"(CC[3]) \
                 : "r"(A0), "r"(A1), "r"(A2), "r"(A3), "r"(B0), "r"(B1))

// ---------------------------------------------------------------------------
// Kernel A: build permuted g_fej; blocks 0-63 also zero accumulators
// ---------------------------------------------------------------------------
__global__ void k_fej(const float* __restrict__ fe,
                      const float* __restrict__ h_w1,
                      const float* __restrict__ h_b1) {
    __shared__ float fes[8][33];
    const int j8 = blockIdx.x;
    const int t  = threadIdx.x;          // 256
    if (j8 < 64) {
        const int i = j8 * 256 + t;
        if (i < BB * 4 * DD) g_num[i] = 0.f;
        if (i < BB * 4)      g_sumexp[i] = 0.f;
        if (i < BB)          g_maskcnt[i] = 0;
    }
    fes[t >> 5][t & 31] = fe[(j8 * 8 + (t >> 5)) * DD + (t & 31)];
    __syncthreads();
    const int f  = 4 * t;
    const int i  = f >> 7;
    const int jc = (f >> 4) & 7;
    const int qq = (f >> 2) & 3;
    const int h0 = 32 * qq + 4 * i;
    float4 acc = *reinterpret_cast<const float4*>(&h_b1[h0]);
    const float* fr = fes[jc];
#pragma unroll 8
    for (int d = 0; d < 32; d++) {
        const float4 wv = *reinterpret_cast<const float4*>(&h_w1[(1 + d) * HH + h0]);
        const float fv = fr[d];
        acc.x = fmaf(fv, wv.x, acc.x);
        acc.y = fmaf(fv, wv.y, acc.y);
        acc.z = fmaf(fv, wv.z, acc.z);
        acc.w = fmaf(fv, wv.w, acc.w);
    }
    *reinterpret_cast<float4*>(&g_fej[j8 * 1024 + f]) = acc;
}

// ---------------------------------------------------------------------------
// Kernel B: persistent pipeline; 4-warp tensor-core GEMM (m16 x n32 per warp)
// with hi/lo bf16 split (3 passes) and in-register LN over D=32.
// ---------------------------------------------------------------------------
__global__ void __launch_bounds__(NT, 3)
k_main(const float* __restrict__ x, const int* __restrict__ mask,
       const float* __restrict__ h_w1,
       const float* __restrict__ h_ln1_w, const float* __restrict__ h_ln1_b,
       const float* __restrict__ h_w2,   const float* __restrict__ h_b2,
       const float* __restrict__ h_ln2_w, const float* __restrict__ h_ln2_b,
       const float* __restrict__ gw1,    const float* __restrict__ gb1,
       const float* __restrict__ gw2,    const float* __restrict__ gb2) {
    extern __shared__ char smc[];
    float* smf = (float*)smc;
    int*   smi = (int*)smc;
    const int t  = threadIdx.x;
    const int c = t >> 2, q = t & 3;
    const int w = t >> 5, lane = t & 31, r0 = w * 8;

    // ---- one-time weight staging ----
    for (int idx = t; idx < HH * DD; idx += NT) {   // w2 -> bf16 hi/lo [d][k]
        const int k = idx >> 5, d = idx & 31;
        const float v = h_w2[idx];
        const __nv_bfloat16 hb = __float2bfloat16_rn(v);
        const float r = v - __bfloat162float(hb);
        *(__nv_bfloat16*)(smc + SB_WHI + d * 272 + 2 * k) = hb;
        *(__nv_bfloat16*)(smc + SB_WLO + d * 272 + 2 * k) = __float2bfloat16_rn(r);
    }
    if (t < HH) {
        smf[F_W10 + t]  = h_w1[t];
        smf[F_LN1W + t] = h_ln1_w[t];
        smf[F_LN1B + t] = h_ln1_b[t];
    }
    if (t < DD) {
        smf[F_LN2W + t] = h_ln2_w[t];
        smf[F_LN2B + t] = h_ln2_b[t];
        smf[F_HB2 + t]  = h_b2[t];
    }
    for (int i = t; i < 512; i += NT) smf[F_GW1 + i] = gw1[i];
    if (t < 16) smf[F_GB1 + t] = gb1[t];
    if (t < 64) smf[F_GW2 + t] = gw2[t];
    if (t < 4)  smf[F_GB2 + t] = gb2[t];

    const float4* fj4 = reinterpret_cast<const float4*>(g_fej);

    // ldmatrix bases (constant across tiles), valid for warps 0-3 (mt = w)
    const uint32_t aAddrHi0 = s2u(smc + SB_H1HI) + (16 * w + (lane & 15)) * 272 + ((lane >> 4) * 16);
    const uint32_t aAddrLo0 = aAddrHi0 + (SB_H1LO - SB_H1HI);
    const uint32_t bRow = 8 * (lane >> 4) + (lane & 7);
    const uint32_t bCol = ((lane >> 3) & 1) * 16;
    const uint32_t bHiG0 = s2u(smc + SB_WHI) + bRow * 272 + bCol;           // n 0-15
    const uint32_t bHiG1 = s2u(smc + SB_WHI) + (16 + bRow) * 272 + bCol;    // n 16-31
    const uint32_t bLoG0 = bHiG0 + (SB_WLO - SB_WHI);
    const uint32_t bLoG1 = bHiG1 + (SB_WLO - SB_WHI);

    for (int tile = blockIdx.x; tile < NTILES; tile += GRID_MAIN) {
        const int b  = tile >> 7;
        const int j0 = (tile & 127) * TJ;

        if (t < TJ) {
            smf[F_XS + t] = x[b * JJ + j0 + t];
            smi[F_MS + t] = mask[b * JJ + j0 + t];
        }
        __syncthreads();   // B1: XS/MS published; prev-iter smem reuse fenced

        // ---- phase 1: pre = x*w1_0 + fej ; LN(128) ; relu -> bf16 hi/lo ----
        {
            const int fbase = ((j0 + c) >> 3) * 256 + (c & 7) * 4 + q;
            const float xv = smf[F_XS + c];
            float4 pv[8];
            float s = 0.f, ss = 0.f;
#pragma unroll
            for (int i = 0; i < 8; i++) {
                float4 f = fj4[fbase + 32 * i];
                const float4 wv = *reinterpret_cast<const float4*>(&smf[F_W10 + q * 32 + 4 * i]);
                float4 v;
                v.x = fmaf(xv, wv.x, f.x);
                v.y = fmaf(xv, wv.y, f.y);
                v.z = fmaf(xv, wv.z, f.z);
                v.w = fmaf(xv, wv.w, f.w);
                pv[i] = v;
                s  += (v.x + v.y) + (v.z + v.w);
                ss += v.x * v.x + v.y * v.y + v.z * v.z + v.w * v.w;
            }
            s  += __shfl_xor_sync(0xffffffffu, s, 1);
            s  += __shfl_xor_sync(0xffffffffu, s, 2);
            ss += __shfl_xor_sync(0xffffffffu, ss, 1);
            ss += __shfl_xor_sync(0xffffffffu, ss, 2);
            const float mean = s * (1.f / 128.f);
            const float var  = ss * (1.f / 128.f) - mean * mean;
            const float rstd = rsqrtf(var + 1e-5f);
            uint32_t hi[16], lo[16];
#pragma unroll
            for (int i = 0; i < 8; i++) {
                float4 v = pv[i];
                const float4 lw = *reinterpret_cast<const float4*>(&smf[F_LN1W + q * 32 + 4 * i]);
                const float4 lb = *reinterpret_cast<const float4*>(&smf[F_LN1B + q * 32 + 4 * i]);
                const float o0 = fmaxf(0.f, fmaf((v.x - mean) * rstd, lw.x, lb.x));
                const float o1 = fmaxf(0.f, fmaf((v.y - mean) * rstd, lw.y, lb.y));
                const float o2 = fmaxf(0.f, fmaf((v.z - mean) * rstd, lw.z, lb.z));
                const float o3 = fmaxf(0.f, fmaf((v.w - mean) * rstd, lw.w, lb.w));
                const __nv_bfloat16 h0 = __float2bfloat16_rn(o0);
                const __nv_bfloat16 h1 = __float2bfloat16_rn(o1);
                const __nv_bfloat16 h2 = __float2bfloat16_rn(o2);
                const __nv_bfloat16 h3 = __float2bfloat16_rn(o3);
                hi[2*i]   = pack_bf16x2(o0, o1);
                hi[2*i+1] = pack_bf16x2(o2, o3);
                lo[2*i]   = pack_bf16x2(o0 - __bfloat162float(h0), o1 - __bfloat162float(h1));
                lo[2*i+1] = pack_bf16x2(o2 - __bfloat162float(h2), o3 - __bfloat162float(h3));
            }
            char* hdst = smc + SB_H1HI + c * 272 + 64 * q;
            char* ldst = smc + SB_H1LO + c * 272 + 64 * q;
#pragma unroll
            for (int sIdx = 0; sIdx < 4; sIdx++) {
                *reinterpret_cast<uint4*>(hdst + 16 * sIdx) =
                    make_uint4(hi[4*sIdx], hi[4*sIdx+1], hi[4*sIdx+2], hi[4*sIdx+3]);
                *reinterpret_cast<uint4*>(ldst + 16 * sIdx) =
                    make_uint4(lo[4*sIdx], lo[4*sIdx+1], lo[4*sIdx+2], lo[4*sIdx+3]);
            }
        }
        __syncthreads();   // B2: h1 planes visible to MMA warps

        // ---- phase 2+3: warps 0-3: m16 x n32 GEMM + in-register LN ----
        if (w < 4) {
            float acc[4][4];
#pragma unroll
            for (int tl = 0; tl < 4; tl++)
#pragma unroll
                for (int p = 0; p < 4; p++) acc[tl][p] = 0.f;
            uint32_t aH = aAddrHi0, aL = aAddrLo0;
            uint32_t b00 = bHiG0, b01 = bHiG1, b10 = bLoG0, b11 = bLoG1;
#pragma unroll
            for (int ks = 0; ks < 8; ks++) {
                uint32_t ah0, ah1, ah2, ah3, al0, al1, al2, al3;
                uint32_t p0, p1, p2, p3, p4, p5, p6, p7;
                uint32_t m0, m1, m2, m3, m4, m5, m6, m7;
                LDSM4(ah0, ah1, ah2, ah3, aH);
                LDSM4(al0, al1, al2, al3, aL);
                LDSM4(p0, p1, p2, p3, b00);
                LDSM4(p4, p5, p6, p7, b01);
                LDSM4(m0, m1, m2, m3, b10);
                LDSM4(m4, m5, m6, m7, b11);
                MMA_BF16(acc[0], ah0, ah1, ah2, ah3, p0, p1);
                MMA_BF16(acc[1], ah0, ah1, ah2, ah3, p2, p3);
                MMA_BF16(acc[2], ah0, ah1, ah2, ah3, p4, p5);
                MMA_BF16(acc[3], ah0, ah1, ah2, ah3, p6, p7);
                MMA_BF16(acc[0], ah0, ah1, ah2, ah3, m0, m1);
                MMA_BF16(acc[1], ah0, ah1, ah2, ah3, m2, m3);
                MMA_BF16(acc[2], ah0, ah1, ah2, ah3, m4, m5);
                MMA_BF16(acc[3], ah0, ah1, ah2, ah3, m6, m7);
                MMA_BF16(acc[0], al0, al1, al2, al3, p0, p1);
                MMA_BF16(acc[1], al0, al1, al2, al3, p2, p3);
                MMA_BF16(acc[2], al0, al1, al2, al3, p4, p5);
                MMA_BF16(acc[3], al0, al1, al2, al3, p6, p7);
                aH += 32; aL += 32; b00 += 32; b01 += 32; b10 += 32; b11 += 32;
            }
            // in-register LN over D=32 for rows rA and rB=rA+8
            const int j3 = lane & 3;
            const int rA = 16 * w + (lane >> 2);
            float vA[8], vB[8];
            float s1A = 0.f, s2A = 0.f, s1B = 0.f, s2B = 0.f;
#pragma unroll
            for (int tl = 0; tl < 4; tl++) {
                const int col0 = 8 * tl + 2 * j3;
                const float2 hb = *reinterpret_cast<const float2*>(&smf[F_HB2 + col0]);
                vA[2*tl]   = acc[tl][0] + hb.x;
                vA[2*tl+1] = acc[tl][1] + hb.y;
                vB[2*tl]   = acc[tl][2] + hb.x;
                vB[2*tl+1] = acc[tl][3] + hb.y;
                s1A += vA[2*tl] + vA[2*tl+1];
                s2A = fmaf(vA[2*tl], vA[2*tl], fmaf(vA[2*tl+1], vA[2*tl+1], s2A));
                s1B += vB[2*tl] + vB[2*tl+1];
                s2B = fmaf(vB[2*tl], vB[2*tl], fmaf(vB[2*tl+1], vB[2*tl+1], s2B));
            }
            s1A += __shfl_xor_sync(0xffffffffu, s1A, 1);
            s1A += __shfl_xor_sync(0xffffffffu, s1A, 2);
            s2A += __shfl_xor_sync(0xffffffffu, s2A, 1);
            s2A += __shfl_xor_sync(0xffffffffu, s2A, 2);
            s1B += __shfl_xor_sync(0xffffffffu, s1B, 1);
            s1B += __shfl_xor_sync(0xffffffffu, s1B, 2);
            s2B += __shfl_xor_sync(0xffffffffu, s2B, 1);
            s2B += __shfl_xor_sync(0xffffffffu, s2B, 2);
            const float meanA = s1A * (1.f / 32.f);
            const float rstdA = rsqrtf(s2A * (1.f / 32.f) - meanA * meanA + 1e-5f);
            const float meanB = s1B * (1.f / 32.f);
            const float rstdB = rsqrtf(s2B * (1.f / 32.f) - meanB * meanB + 1e-5f);
#pragma unroll
            for (int tl = 0; tl < 4; tl++) {
                const int col0 = 8 * tl + 2 * j3;
                const float2 lw = *reinterpret_cast<const float2*>(&smf[F_LN2W + col0]);
                const float2 lb = *reinterpret_cast<const float2*>(&smf[F_LN2B + col0]);
                float2 oA, oB;
                oA.x = fmaxf(0.f, fmaf((vA[2*tl]   - meanA) * rstdA, lw.x, lb.x));
                oA.y = fmaxf(0.f, fmaf((vA[2*tl+1] - meanA) * rstdA, lw.y, lb.y));
                oB.x = fmaxf(0.f, fmaf((vB[2*tl]   - meanB) * rstdB, lw.x, lb.x));
                oB.y = fmaxf(0.f, fmaf((vB[2*tl+1] - meanB) * rstdB, lw.y, lb.y));
                *reinterpret_cast<float2*>(&smf[F_HOUT + rA * 36 + col0])       = oA;
                *reinterpret_cast<float2*>(&smf[F_HOUT + (rA + 8) * 36 + col0]) = oB;
            }
        }
        __syncthreads();   // B3: hout visible to all warps

        // ---- phase 4: gate MLP -> logits -> clip -> mask -> exp ----
        float se;
        int   cnt;
        {
            const float4* hrow4 = reinterpret_cast<const float4*>(&smf[F_HOUT + c * 36]);
            float g1v[4];
#pragma unroll
            for (int e = 0; e < 4; e++) g1v[e] = smf[F_GB1 + 4 * q + e];
#pragma unroll
            for (int i = 0; i < 8; i++) {
                const float4 h4 = hrow4[i];
#pragma unroll
                for (int ccc = 0; ccc < 4; ccc++) {
                    const float hvv = (ccc == 0) ? h4.x : (ccc == 1) ? h4.y : (ccc == 2) ? h4.z : h4.w;
                    const float4 gw = *reinterpret_cast<const float4*>(&smf[F_GW1 + (4 * i + ccc) * 16 + 4 * q]);
                    g1v[0] = fmaf(hvv, gw.x, g1v[0]);
                    g1v[1] = fmaf(hvv, gw.y, g1v[1]);
                    g1v[2] = fmaf(hvv, gw.z, g1v[2]);
                    g1v[3] = fmaf(hvv, gw.w, g1v[3]);
                }
            }
            float pl[4] = {0.f, 0.f, 0.f, 0.f};
#pragma unroll
            for (int e = 0; e < 4; e++) {
                const float gv = fmaxf(0.f, g1v[e]);
                const float4 g2 = *reinterpret_cast<const float4*>(&smf[F_GW2 + (4 * q + e) * 4]);
                pl[0] = fmaf(gv, g2.x, pl[0]);
                pl[1] = fmaf(gv, g2.y, pl[1]);
                pl[2] = fmaf(gv, g2.z, pl[2]);
                pl[3] = fmaf(gv, g2.w, pl[3]);
            }
#pragma unroll
            for (int k = 0; k < 4; k++) {
                pl[k] += __shfl_xor_sync(0xffffffffu, pl[k], 1);
                pl[k] += __shfl_xor_sync(0xffffffffu, pl[k], 2);
            }
            const int mval = smi[F_MS + c];
            const float raw = pl[q] + smf[F_GB2 + q];
            const float lgt = fminf(10.f, fmaxf(-10.f, raw));
            const float ev  = (mval > 0) ? __expf(lgt) : 0.f;
            smf[F_ELOG + c * 4 + q] = ev;
            se = ev;
            se += __shfl_xor_sync(0xffffffffu, se, 4);
            se += __shfl_xor_sync(0xffffffffu, se, 8);
            se += __shfl_xor_sync(0xffffffffu, se, 16);
            const unsigned bal = __ballot_sync(0xffffffffu, (q == 0) && (mval > 0));
            cnt = (int)__popc(bal);
        }
        __syncwarp();

        // ---- phase 5: pooling partials into warp-own scratch ----
        {
            float p0 = 0.f, p1 = 0.f, p2 = 0.f, p3 = 0.f;
#pragma unroll
            for (int rr = 0; rr < 8; rr++) {
                const float4 ev = *reinterpret_cast<const float4*>(&smf[F_ELOG + (r0 + rr) * 4]);
                const float h = smf[F_HOUT + (r0 + rr) * 36 + lane];
                p0 = fmaf(ev.x, h, p0);
                p1 = fmaf(ev.y, h, p1);
                p2 = fmaf(ev.z, h, p2);
                p3 = fmaf(ev.w, h, p3);
            }
            float* wn = &smf[F_WPOOL + w * 136];
            wn[0 * 32 + lane] = p0;
            wn[1 * 32 + lane] = p1;
            wn[2 * 32 + lane] = p2;
            wn[3 * 32 + lane] = p3;
            if (lane < 4) wn[128 + lane] = se;
            if (lane == 0) ((int*)wn)[132] = cnt;
        }
        __syncthreads();   // B4

        // ---- phase 6: cross-warp reduce + global RED ----
        if (t < 128) {
            float a = 0.f;
#pragma unroll
            for (int ww = 0; ww < 8; ww++) a += smf[F_WPOOL + ww * 136 + t];
            atomicAdd(&g_num[b * 128 + t], a);
        } else if (t < 132) {
            const int hq = t - 128;
            float a = 0.f;
#pragma unroll
            for (int ww = 0; ww < 8; ww++) a += smf[F_WPOOL + ww * 136 + 128 + hq];
            atomicAdd(&g_sumexp[b * 4 + hq], a);
        } else if (t == 132) {
            int a = 0;
#pragma unroll
            for (int ww = 0; ww < 8; ww++) a += ((int*)&smf[F_WPOOL + ww * 136])[132];
            atomicAdd(&g_maskcnt[b], a);
        }
    }
}

// ---------------------------------------------------------------------------
// Kernel C: per-batch tail  head_sums -> comb -> e1 -> e2 -> (mu, logvar)
// ---------------------------------------------------------------------------
__global__ void k_tail(const float* __restrict__ c_w,    const float* __restrict__ c_b,
                       const float* __restrict__ c_ln_w, const float* __restrict__ c_ln_b,
                       const float* __restrict__ e_w1,   const float* __restrict__ e_b1,
                       const float* __restrict__ e_ln1_w, const float* __restrict__ e_ln1_b,
                       const float* __restrict__ e_w2,   const float* __restrict__ e_b2,
                       const float* __restrict__ e_ln2_w, const float* __restrict__ e_ln2_b,
                       float* __restrict__ out) {
    const int b = blockIdx.x;
    const int t = threadIdx.x;      // 256
    __shared__ float hs[128];
    __shared__ float comb[32];
    __shared__ float h2s[256];
    __shared__ float red[16];
    __shared__ float part[256];

    const int mc = g_maskcnt[b];
    if (t < 128) {
        const float den = g_sumexp[b * 4 + (t >> 5)];
        hs[t] = (mc > 0) ? g_num[b * 128 + t] / den : 0.f;
    }
    __syncthreads();

    {
        const int o = t & 31, kg = t >> 5;
        float a = 0.f;
#pragma unroll
        for (int k = 0; k < 16; k++)
            a = fmaf(hs[kg * 16 + k], c_w[(kg * 16 + k) * 32 + o], a);
        part[kg * 32 + o] = a;
    }
    __syncthreads();
    if (t < 32) {
        float a = c_b[t];
#pragma unroll
        for (int g = 0; g < 8; g++) a += part[g * 32 + t];
        float s1 = a, s2 = a * a;
#pragma unroll
        for (int m = 16; m > 0; m >>= 1) {
            s1 += __shfl_xor_sync(0xffffffffu, s1, m);
            s2 += __shfl_xor_sync(0xffffffffu, s2, m);
        }
        const float mean = s1 * (1.f / 32.f);
        const float var  = s2 * (1.f / 32.f) - mean * mean;
        const float r = rsqrtf(var + 1e-5f);
        const float v = fmaxf(0.f, fmaf((a - mean) * r, c_ln_w[t], c_ln_b[t]));
        comb[t] = (mc > 0) ? v : 0.f;
    }
    __syncthreads();

    {
        float a = e_b1[t];
#pragma unroll
        for (int k = 0; k < 32; k++) a = fmaf(comb[k], e_w1[k * 256 + t], a);
        float s1 = a, s2 = a * a;
#pragma unroll
        for (int m = 16; m > 0; m >>= 1) {
            s1 += __shfl_xor_sync(0xffffffffu, s1, m);
            s2 += __shfl_xor_sync(0xffffffffu, s2, m);
        }
        if ((t & 31) == 0) { red[t >> 5] = s1; red[8 + (t >> 5)] = s2; }
        __syncthreads();
        float S = 0.f, SS = 0.f;
#pragma unroll
        for (int i = 0; i < 8; i++) { S += red[i]; SS += red[8 + i]; }
        const float mean = S * (1.f / 256.f);
        const float var  = SS * (1.f / 256.f) - mean * mean;
        const float r = rsqrtf(var + 1e-5f);
        h2s[t] = fmaxf(0.f, fmaf((a - mean) * r, e_ln1_w[t], e_ln1_b[t]));
    }
    __syncthreads();

    {
        const int o = t & 63, kg = t >> 6;
        float a = 0.f;
#pragma unroll 8
        for (int k = 0; k < 64; k++)
            a = fmaf(h2s[kg * 64 + k], e_w2[(kg * 64 + k) * 64 + o], a);
        part[kg * 64 + o] = a;
    }
    __syncthreads();
    float oacc = 0.f;
    if (t < 64) {
        oacc = e_b2[t] + part[t] + part[64 + t] + part[128 + t] + part[192 + t];
        float s1 = oacc, s2 = oacc * oacc;
#pragma unroll
        for (int m = 16; m > 0; m >>= 1) {
            s1 += __shfl_xor_sync(0xffffffffu, s1, m);
            s2 += __shfl_xor_sync(0xffffffffu, s2, m);
        }
        if ((t & 31) == 0) { red[t >> 5] = s1; red[8 + (t >> 5)] = s2; }
    }
    __syncthreads();
    if (t < 64) {
        const float S  = red[0] + red[1];
        const float SS = red[8] + red[9];
        const float mean = S * (1.f / 64.f);
        const float var  = SS * (1.f / 64.f) - mean * mean;
        const float r = rsqrtf(var + 1e-5f);
        const float o = fmaxf(0.f, fmaf((oacc - mean) * r, e_ln2_w[t], e_ln2_b[t]));
        out[(t >> 5) * (BB * 32) + b * 32 + (t & 31)] = o;
    }
}

// ---------------------------------------------------------------------------
// Launch: 3 kernels, no pads
// ---------------------------------------------------------------------------
extern "C" void kernel_launch(void* const* d_in, const int* in_sizes, int n_in,
                              void* d_out, int out_size) {
    const float* x       = (const float*)d_in[0];
    const int*   mask    = (const int*)  d_in[1];
    const float* fe      = (const float*)d_in[2];
    const float* h_w1    = (const float*)d_in[3];
    const float* h_b1    = (const float*)d_in[4];
    const float* h_ln1_w = (const float*)d_in[5];
    const float* h_ln1_b = (const float*)d_in[6];
    const float* h_w2    = (const float*)d_in[7];
    const float* h_b2    = (const float*)d_in[8];
    const float* h_ln2_w = (const float*)d_in[9];
    const float* h_ln2_b = (const float*)d_in[10];
    const float* g_w1    = (const float*)d_in[11];
    const float* g_b1    = (const float*)d_in[12];
    const float* g_w2    = (const float*)d_in[13];
    const float* g_b2    = (const float*)d_in[14];
    const float* c_w     = (const float*)d_in[15];
    const float* c_b     = (const float*)d_in[16];
    const float* c_ln_w  = (const float*)d_in[17];
    const float* c_ln_b  = (const float*)d_in[18];
    const float* e_w1    = (const float*)d_in[19];
    const float* e_b1    = (const float*)d_in[20];
    const float* e_ln1_w = (const float*)d_in[21];
    const float* e_ln1_b = (const float*)d_in[22];
    const float* e_w2    = (const float*)d_in[23];
    const float* e_b2    = (const float*)d_in[24];
    const float* e_ln2_w = (const float*)d_in[25];
    const float* e_ln2_b = (const float*)d_in[26];
    float* out = (float*)d_out;

    cudaFuncSetAttribute(k_main, cudaFuncAttributeMaxDynamicSharedMemorySize, SMEM_BYTES);

    k_fej<<<JJ / 8, 256>>>(fe, h_w1, h_b1);
    k_main<<<GRID_MAIN, NT, SMEM_BYTES>>>(x, mask, h_w1, h_ln1_w, h_ln1_b,
                                          h_w2, h_b2, h_ln2_w, h_ln2_b,
                                          g_w1, g_b1, g_w2, g_b2);
    k_tail<<<BB, 256>>>(c_w, c_b, c_ln_w, c_ln_b,
                        e_w1, e_b1, e_ln1_w, e_ln1_b,
                        e_w2, e_b2, e_ln2_w, e_ln2_b, out);
}